// round 14
// baseline (speedup 1.0000x reference)
#include <cuda_runtime.h>
#include <cuda_fp16.h>
#include <cstdint>

#define HW 128
#define KSZ 255
#define NTHR 256

// smem byte offsets
#define OFF_WHP 0        // 254 fp16-pairs of wh
#define OFF_WWP 1024     // 254 fp16-pairs of ww
#define OFF_X   4096     // X^T fp16 plane, 128 rows (32KB)
#define SMEM_TOTAL 36864 // 36KB -> 3 CTAs/SM

// K-major fp16 plane: rows x 256B; 16B chunks XOR-swizzled by row&7.
__device__ __forceinline__ uint32_t off_rk(int r, int k) {
    return (uint32_t)(r * 256 + ((((k >> 3) ^ (r & 7)) << 4) | ((k & 7) << 1)));
}

__device__ __forceinline__ uint32_t s2u(const void* p) {
    uint32_t a;
    asm("{ .reg .u64 t; cvta.to.shared.u64 t, %1; cvt.u32.u64 %0, t; }" : "=r"(a) : "l"(p));
    return a;
}

__device__ __forceinline__ void ldsm4(uint32_t* r, uint32_t a) {
    asm volatile("ldmatrix.sync.aligned.m8n8.x4.shared.b16 {%0,%1,%2,%3},[%4];"
                 : "=r"(r[0]), "=r"(r[1]), "=r"(r[2]), "=r"(r[3]) : "r"(a));
}

__device__ __forceinline__ void mma_f16(float* d, uint32_t a0, uint32_t a1, uint32_t a2,
                                        uint32_t a3, uint32_t b0, uint32_t b1) {
    asm volatile(
        "mma.sync.aligned.m16n8k16.row.col.f32.f16.f16.f32 "
        "{%0,%1,%2,%3},{%4,%5,%6,%7},{%8,%9},{%0,%1,%2,%3};"
        : "+f"(d[0]), "+f"(d[1]), "+f"(d[2]), "+f"(d[3])
        : "r"(a0), "r"(a1), "r"(a2), "r"(a3), "r"(b0), "r"(b1));
}

__device__ __forceinline__ uint32_t pack2(float a, float b) {
    __half2 h = __floats2half2_rn(a, b);
    return *(uint32_t*)&h;
}

__device__ __forceinline__ uint32_t lds32(uint32_t addr) {
    uint32_t v;
    asm volatile("ld.shared.b32 %0, [%1];" : "=r"(v) : "r"(addr));
    return v;
}

extern "C" __global__ void __launch_bounds__(NTHR, 3)
conv_mma_kernel(const float* __restrict__ x,
                const float* __restrict__ wh, const float* __restrict__ bh,
                const float* __restrict__ ww, const float* __restrict__ bw,
                float* __restrict__ out) {
    extern __shared__ __align__(1024) char smem[];
    uint32_t sb = s2u(smem);
    int t = threadIdx.x, lane = t & 31, wid = t >> 5;
    int img = blockIdx.x, c = img & 255;
    size_t base = (size_t)img << 14;

    // Weight pair tables: p[i] = (f16(w[i]), f16(w[i+1])), i in [0,253].
    if (t < KSZ - 1) {
        const float* wp = wh + c * KSZ;
        *(uint32_t*)(smem + OFF_WHP + 4 * t) = pack2(wp[t], wp[t + 1]);
        wp = ww + c * KSZ;
        *(uint32_t*)(smem + OFF_WWP + 4 * t) = pack2(wp[t], wp[t + 1]);
    }
    float bhc = bh[c], bwc = bw[c];

    // X^T fp16 plane: plane[w][i] = f16(X[i][w]); one STS.128 per 8-i chunk.
    {
        int w = t & 127, ihalf = t >> 7;
        const float* xp = x + base + w;
#pragma unroll
        for (int blk = 0; blk < 8; blk++) {
            int i0 = ihalf * 64 + blk * 8;
            uint32_t q[4];
#pragma unroll
            for (int j = 0; j < 4; j++) {
                float f0 = xp[(size_t)(i0 + 2 * j) * HW];
                float f1 = xp[(size_t)(i0 + 2 * j + 1) * HW];
                q[j] = pack2(f0, f1);
            }
            *(uint4*)(smem + OFF_X + off_rk(w, i0)) = *(uint4*)q;
        }
    }
    __syncthreads();   // the ONLY barrier

    int g = lane >> 2, tt2 = (lane & 3) * 2;
    int mbase = wid * 16;             // warp owns output rows mbase..mbase+15
    int nB = lane & 7, khB = (lane & 15) >> 3, tB = lane >> 4;
    uint32_t pwh = sb + OFF_WHP, pww = sb + OFF_WWP;

    // ---- Stage 1: Y[h][w] = Toep(wh) @ X, in two n-halves of 64 cols. ----
    uint32_t fA[8][4];
    int ib1 = 127 + tt2 - g - mbase;               // in [8, 133]
    uint32_t bRow = (uint32_t)(8 * tB + nB) * 256;

#pragma unroll
    for (int h = 0; h < 2; h++) {
        float d1h[8][4];
#pragma unroll
        for (int tn = 0; tn < 8; tn++)
#pragma unroll
            for (int q = 0; q < 4; q++) d1h[tn][q] = bhc;

        uint32_t W1a = lds32(pwh + 4u * (uint32_t)(ib1 - 8));
        uint32_t W1b = lds32(pwh + 4u * (uint32_t)(ib1));
        uint32_t W1c = lds32(pwh + 4u * (uint32_t)(ib1 + 8));
#pragma unroll
        for (int kk = 0; kk < 8; kk++) {
            if (kk) {
                W1a = W1c;
                W1b = lds32(pwh + 4u * (uint32_t)(ib1 + 16 * kk));
                W1c = lds32(pwh + 4u * (uint32_t)(ib1 + 16 * kk + 8));
            }
            uint32_t bx = (uint32_t)(((2 * kk + khB) ^ nB) << 4);
#pragma unroll
            for (int sub = 0; sub < 2; sub++) {
                int gg0 = 4 * h + 2 * sub;
                uint32_t bb[2][4];
                ldsm4(bb[0], sb + OFF_X + bRow + (uint32_t)gg0 * 4096 + bx);
                ldsm4(bb[1], sb + OFF_X + bRow + (uint32_t)(gg0 + 1) * 4096 + bx);
#pragma unroll
                for (int ltn = 0; ltn < 4; ltn++)
                    mma_f16(d1h[4 * sub + ltn], W1b, W1a, W1c, W1b,
                            bb[ltn >> 1][(ltn & 1) * 2], bb[ltn >> 1][(ltn & 1) * 2 + 1]);
            }
        }
        // Pack this half's Y into stage-2 A fragments (d1h dies here).
#pragma unroll
        for (int p = 0; p < 4; p++) {
            fA[4 * h + p][0] = pack2(d1h[2 * p][0], d1h[2 * p][1]);
            fA[4 * h + p][1] = pack2(d1h[2 * p][2], d1h[2 * p][3]);
            fA[4 * h + p][2] = pack2(d1h[2 * p + 1][0], d1h[2 * p + 1][1]);
            fA[4 * h + p][3] = pack2(d1h[2 * p + 1][2], d1h[2 * p + 1][3]);
        }
    }

    // ---- Stage 2: Z[h][w'] = Y @ Toep(ww)^T, in two n-halves of 64 cols. ----
    int ib2 = 7 + tt2 - g;                         // in [0, 13]
#pragma unroll
    for (int h = 0; h < 2; h++) {
        int b = h ? 0 : 8;
        float d2h[8][4];
#pragma unroll
        for (int tn = 0; tn < 8; tn++)
#pragma unroll
            for (int q = 0; q < 4; q++) d2h[tn][q] = bwc;

        uint32_t R[9];
#pragma unroll
        for (int i = 0; i < 9; i++)
            R[i] = lds32(pww + 4u * (uint32_t)(ib2 + 8 * (b + i)));

#pragma unroll
        for (int q = 0; q < 8; q++) {
            if (q) {
#pragma unroll
                for (int i = 0; i < 7; i++) R[i] = R[i + 2];
                R[7] = lds32(pww + 4u * (uint32_t)(ib2 + 8 * (2 * q + b + 7)));
                R[8] = lds32(pww + 4u * (uint32_t)(ib2 + 8 * (2 * q + b + 8)));
            }
#pragma unroll
            for (int tn = 0; tn < 8; tn++)
                mma_f16(d2h[tn], fA[q][0], fA[q][1], fA[q][2], fA[q][3],
                        R[7 - tn], R[8 - tn]);
        }

        // Store this half's columns.
        {
            int r0 = mbase + g;
#pragma unroll
            for (int tn = 0; tn < 8; tn++) {
                int cc = 64 * h + 8 * tn + tt2;
                *(float2*)(out + base + (size_t)r0 * HW + cc) =
                    make_float2(d2h[tn][0], d2h[tn][1]);
                *(float2*)(out + base + (size_t)(r0 + 8) * HW + cc) =
                    make_float2(d2h[tn][2], d2h[tn][3]);
            }
        }
    }
}

extern "C" void kernel_launch(void* const* d_in, const int* in_sizes, int n_in,
                              void* d_out, int out_size) {
    const float* x  = (const float*)d_in[0];
    const float* wh = (const float*)d_in[1];
    const float* bh = (const float*)d_in[2];
    const float* ww = (const float*)d_in[3];
    const float* bw = (const float*)d_in[4];
    float* out = (float*)d_out;

    int nimg = in_sizes[0] >> 14;
    cudaFuncSetAttribute(conv_mma_kernel,
                         cudaFuncAttributeMaxDynamicSharedMemorySize, SMEM_TOTAL);
    conv_mma_kernel<<<nimg, NTHR, SMEM_TOTAL>>>(x, wh, bh, ww, bw, out);
}

// round 15
// speedup vs baseline: 1.2764x; 1.2764x over previous
#include <cuda_runtime.h>
#include <cuda_fp16.h>
#include <cstdint>

#define HW 128
#define KSZ 255
#define NTHR 256

// smem byte offsets
#define OFF_WHP 0        // 254 fp16-pairs of wh
#define OFF_WWP 1024     // 254 fp16-pairs of ww
#define OFF_X   4096     // X^T fp16 plane, 128 rows (32KB)
#define SMEM_TOTAL 36864

// K-major fp16 plane: rows x 256B; 16B chunks XOR-swizzled by row&7.
__device__ __forceinline__ uint32_t off_rk(int r, int k) {
    return (uint32_t)(r * 256 + ((((k >> 3) ^ (r & 7)) << 4) | ((k & 7) << 1)));
}

__device__ __forceinline__ uint32_t s2u(const void* p) {
    uint32_t a;
    asm("{ .reg .u64 t; cvta.to.shared.u64 t, %1; cvt.u32.u64 %0, t; }" : "=r"(a) : "l"(p));
    return a;
}

__device__ __forceinline__ void ldsm4(uint32_t* r, uint32_t a) {
    asm volatile("ldmatrix.sync.aligned.m8n8.x4.shared.b16 {%0,%1,%2,%3},[%4];"
                 : "=r"(r[0]), "=r"(r[1]), "=r"(r[2]), "=r"(r[3]) : "r"(a));
}

__device__ __forceinline__ void mma_f16(float* d, uint32_t a0, uint32_t a1, uint32_t a2,
                                        uint32_t a3, uint32_t b0, uint32_t b1) {
    asm volatile(
        "mma.sync.aligned.m16n8k16.row.col.f32.f16.f16.f32 "
        "{%0,%1,%2,%3},{%4,%5,%6,%7},{%8,%9},{%0,%1,%2,%3};"
        : "+f"(d[0]), "+f"(d[1]), "+f"(d[2]), "+f"(d[3])
        : "r"(a0), "r"(a1), "r"(a2), "r"(a3), "r"(b0), "r"(b1));
}

__device__ __forceinline__ uint32_t pack2(float a, float b) {
    __half2 h = __floats2half2_rn(a, b);
    return *(uint32_t*)&h;
}

__device__ __forceinline__ uint32_t lds32(uint32_t addr) {
    uint32_t v;
    asm volatile("ld.shared.b32 %0, [%1];" : "=r"(v) : "r"(addr));
    return v;
}

__device__ __forceinline__ float ldg_cs(const float* p) {
    float v;
    asm volatile("ld.global.cs.f32 %0, [%1];" : "=f"(v) : "l"(p));
    return v;
}

__device__ __forceinline__ void stg_cs64(float* p, float a, float b) {
    float2 v = make_float2(a, b);
    asm volatile("st.global.cs.v2.f32 [%0], {%1, %2};" :: "l"(p), "f"(v.x), "f"(v.y)
                 : "memory");
}

extern "C" __global__ void __launch_bounds__(NTHR, 2)
conv_mma_kernel(const float* __restrict__ x,
                const float* __restrict__ wh, const float* __restrict__ bh,
                const float* __restrict__ ww, const float* __restrict__ bw,
                float* __restrict__ out) {
    extern __shared__ __align__(1024) char smem[];
    uint32_t sb = s2u(smem);
    int t = threadIdx.x, lane = t & 31, wid = t >> 5;
    int img = blockIdx.x, c = img & 255;
    size_t base = (size_t)img << 14;

    // Weight pair tables: p[i] = (f16(w[i]), f16(w[i+1])), i in [0,253].
    if (t < KSZ - 1) {
        const float* wp = wh + c * KSZ;
        *(uint32_t*)(smem + OFF_WHP + 4 * t) = pack2(wp[t], wp[t + 1]);
        wp = ww + c * KSZ;
        *(uint32_t*)(smem + OFF_WWP + 4 * t) = pack2(wp[t], wp[t + 1]);
    }
    float bhc = bh[c], bwc = bw[c];

    // X^T fp16 plane: plane[w][i] = f16(X[i][w]); one STS.128 per 8-i chunk.
    // X is single-use -> evict-first loads keep L2 for weights/biases.
    {
        int w = t & 127, ihalf = t >> 7;
        const float* xp = x + base + w;
#pragma unroll
        for (int blk = 0; blk < 8; blk++) {
            int i0 = ihalf * 64 + blk * 8;
            float f[8];
#pragma unroll
            for (int j = 0; j < 8; j++) f[j] = ldg_cs(xp + (size_t)(i0 + j) * HW);
            uint32_t q[4];
#pragma unroll
            for (int j = 0; j < 4; j++) q[j] = pack2(f[2 * j], f[2 * j + 1]);
            *(uint4*)(smem + OFF_X + off_rk(w, i0)) = *(uint4*)q;
        }
    }
    __syncthreads();   // the ONLY barrier

    int g = lane >> 2, tt2 = (lane & 3) * 2;
    int mbase = wid * 16;             // warp owns output rows mbase..mbase+15
    int nB = lane & 7, khB = (lane & 15) >> 3, tB = lane >> 4;
    uint32_t pwh = sb + OFF_WHP, pww = sb + OFF_WWP;

    // ---- Stage 1: Y[h][w] = Toep(wh) @ X, rows mbase..mbase+15, all 128 w. ----
    float d1[16][4];
#pragma unroll
    for (int tn = 0; tn < 16; tn++)
#pragma unroll
        for (int q = 0; q < 4; q++) d1[tn][q] = bhc;

    {
        int ib1 = 127 + tt2 - g - mbase;           // in [8, 133]
        uint32_t W1a = lds32(pwh + 4u * (uint32_t)(ib1 - 8));
        uint32_t W1b = lds32(pwh + 4u * (uint32_t)(ib1));
        uint32_t W1c = lds32(pwh + 4u * (uint32_t)(ib1 + 8));
        uint32_t bRow = (uint32_t)(8 * tB + nB) * 256;
#pragma unroll
        for (int kk = 0; kk < 8; kk++) {
            if (kk) {
                W1a = W1c;
                W1b = lds32(pwh + 4u * (uint32_t)(ib1 + 16 * kk));
                W1c = lds32(pwh + 4u * (uint32_t)(ib1 + 16 * kk + 8));
            }
            uint32_t bx = (uint32_t)(((2 * kk + khB) ^ nB) << 4);
            uint32_t bb[8][4];
#pragma unroll
            for (int gg = 0; gg < 8; gg++)
                ldsm4(bb[gg], sb + OFF_X + bRow + (uint32_t)gg * 4096 + bx);
#pragma unroll
            for (int tn = 0; tn < 16; tn++)
                mma_f16(d1[tn], W1b, W1a, W1c, W1b,
                        bb[tn >> 1][(tn & 1) * 2], bb[tn >> 1][(tn & 1) * 2 + 1]);
        }
    }

    // In-register handoff: Y (f32 accums) -> stage-2 A-fragments (fp16x2).
    uint32_t fA[8][4];
#pragma unroll
    for (int q = 0; q < 8; q++) {
        fA[q][0] = pack2(d1[2 * q][0], d1[2 * q][1]);
        fA[q][1] = pack2(d1[2 * q][2], d1[2 * q][3]);
        fA[q][2] = pack2(d1[2 * q + 1][0], d1[2 * q + 1][1]);
        fA[q][3] = pack2(d1[2 * q + 1][2], d1[2 * q + 1][3]);
    }

    // ---- Stage 2: Z[h][w'] = Y @ Toep(ww)^T, same rows, all 128 w'. ----
    float d2[16][4];
#pragma unroll
    for (int tn = 0; tn < 16; tn++)
#pragma unroll
        for (int q = 0; q < 4; q++) d2[tn][q] = bwc;

    {
        int ib2 = 7 + tt2 - g;                    // in [0, 13]
        uint32_t W2[17];                          // W2[j] = tab[ib2 + 8*(2q + j)]
#pragma unroll
        for (int j = 0; j < 17; j++) W2[j] = lds32(pww + 4u * (uint32_t)(ib2 + 8 * j));
#pragma unroll
        for (int q = 0; q < 8; q++) {
            if (q) {
#pragma unroll
                for (int j = 0; j < 15; j++) W2[j] = W2[j + 2];
                W2[15] = lds32(pww + 4u * (uint32_t)(ib2 + 8 * (2 * q + 15)));
                W2[16] = lds32(pww + 4u * (uint32_t)(ib2 + 8 * (2 * q + 16)));
            }
#pragma unroll
            for (int tn = 0; tn < 16; tn++)
                mma_f16(d2[tn], fA[q][0], fA[q][1], fA[q][2], fA[q][3],
                        W2[15 - tn], W2[16 - tn]);
        }
    }

    // Final epilogue: Z -> global, streaming stores (never re-read).
    {
        int r0 = mbase + g;
#pragma unroll
        for (int tn = 0; tn < 16; tn++) {
            int c0 = 8 * tn + tt2;
            stg_cs64(out + base + (size_t)r0 * HW + c0, d2[tn][0], d2[tn][1]);
            stg_cs64(out + base + (size_t)(r0 + 8) * HW + c0, d2[tn][2], d2[tn][3]);
        }
    }
}

extern "C" void kernel_launch(void* const* d_in, const int* in_sizes, int n_in,
                              void* d_out, int out_size) {
    const float* x  = (const float*)d_in[0];
    const float* wh = (const float*)d_in[1];
    const float* bh = (const float*)d_in[2];
    const float* ww = (const float*)d_in[3];
    const float* bw = (const float*)d_in[4];
    float* out = (float*)d_out;

    int nimg = in_sizes[0] >> 14;
    cudaFuncSetAttribute(conv_mma_kernel,
                         cudaFuncAttributeMaxDynamicSharedMemorySize, SMEM_TOTAL);
    conv_mma_kernel<<<nimg, NTHR, SMEM_TOTAL>>>(x, wh, bh, ww, bw, out);
}